// round 16
// baseline (speedup 1.0000x reference)
#include <cuda_runtime.h>
#include <cuda_fp16.h>
#include <cstdint>

#define D_IN   1024
#define D_OUTD 1024
#define NTREES 12
#define NINT   7
#define NCOL   96      // 84 decision cols + 12 gate cols; also 12 trees * 8 leaves
#define NHEADS 3
#define MAX_TOK 8192

// scratch
__device__ __half   g_coefh[MAX_TOK * NCOL];        // [tok][j]  (k2 A operand, fp16)
__device__ __half   g_loth[NHEADS * D_OUTD * NCOL]; // [h][d][j] (k2 B operand, fp16)
__device__ uint32_t g_whu[NCOL * (D_IN / 2)];       // fp16x2 weights [96][1024]

__device__ __forceinline__ uint32_t smem_u32(const void* p) {
    uint32_t a;
    asm("{ .reg .u64 t; cvta.to.shared.u64 t, %1; cvt.u32.u64 %0, t; }" : "=r"(a) : "l"(p));
    return a;
}
__device__ __forceinline__ void cpasync16(uint32_t dst, const void* src) {
    asm volatile("cp.async.cg.shared.global [%0], [%1], 16;" :: "r"(dst), "l"(src) : "memory");
}

#define MMA_F16(acc, a, b)                                                      \
    asm("mma.sync.aligned.m16n8k16.row.col.f32.f16.f16.f32 "                    \
        "{%0,%1,%2,%3}, {%4,%5,%6,%7}, {%8,%9}, {%0,%1,%2,%3};"                 \
        : "+f"((acc)[0]), "+f"((acc)[1]), "+f"((acc)[2]), "+f"((acc)[3])        \
        : "r"((a)[0]), "r"((a)[1]), "r"((a)[2]), "r"((a)[3]),                   \
          "r"((b)[0]), "r"((b)[1]))

#define LDMX4(r0, r1, r2, r3, addr)                                             \
    asm volatile("ldmatrix.sync.aligned.m8n8.x4.shared.b16 {%0,%1,%2,%3}, [%4];"\
        : "=r"(r0), "=r"(r1), "=r"(r2), "=r"(r3) : "r"(addr))

#define LDMX2(r0, r1, addr)                                                     \
    asm volatile("ldmatrix.sync.aligned.m8n8.x2.shared.b16 {%0,%1}, [%2];"      \
        : "=r"(r0), "=r"(r1) : "r"(addr))

// ---------------------------------------------------------------------------
// Prep kernel: blocks 0..95 convert weights to fp16;
//              blocks 96..383 transpose LO -> fp16 [h][d][j]   (R15 verbatim)
// ---------------------------------------------------------------------------
__global__ void k_prep(const float* __restrict__ dw, const float* __restrict__ gw,
                       const float* __restrict__ lo)
{
    const int b = blockIdx.x;
    if (b < NCOL) {
        const int row = b;
        const float* src = (row < 84) ? (dw + (size_t)row * D_IN)
                                      : (gw + (size_t)(row - 84) * D_IN);
        for (int k = threadIdx.x * 4; k < D_IN; k += blockDim.x * 4) {
            float4 v = *(const float4*)&src[k];
            __half2 h0 = __floats2half2_rn(v.x, v.y);
            __half2 h1 = __floats2half2_rn(v.z, v.w);
            uint32_t o = (uint32_t)(row * D_IN + k) >> 1;
            g_whu[o] = *(uint32_t*)&h0;
            g_whu[o + 1] = *(uint32_t*)&h1;
        }
    } else {
        __shared__ float t[32][33];
        const int tt = b - NCOL;                    // 0..287
        const int d0 = (tt & 31) * 32;
        const int j0 = ((tt >> 5) % 3) * 32;
        const int h  = tt / 96;
        const int tx = threadIdx.x & 31, ty = threadIdx.x >> 5;  // 32 x 8
#pragma unroll
        for (int i = 0; i < 32; i += 8)
            t[ty + i][tx] = lo[((size_t)h * NCOL + (j0 + ty + i)) * D_OUTD + d0 + tx];
        __syncthreads();
#pragma unroll
        for (int i = 0; i < 32; i += 8)
            g_loth[((size_t)h * D_OUTD + (d0 + ty + i)) * NCOL + j0 + tx] =
                __float2half_rn(t[tx][ty + i]);
    }
}

// ---------------------------------------------------------------------------
// Kernel 1: routing GEMM (R15 verbatim).  32-tok CTAs, single fp16 operands,
//   3-stage cp.async, 256 CTAs, 2 CTAs/SM.
// ---------------------------------------------------------------------------
#define T1     256
#define KC1    64
#define STG1B  23040
#define XH_B   69120u
#define CST_F  18432
#define SMEM1  (73728 + 768)

__device__ __forceinline__ void k1_stage(uint32_t base, const float* x, int tokbase,
                                          int kb, int tid)
{
#pragma unroll
    for (int i = 0; i < 2; i++) {                 // x raw: 32 rows x 16 float4
        int idx = i * T1 + tid;
        int row = idx >> 4, c4 = idx & 15;
        cpasync16(base + (uint32_t)(row * 72 + 4 * c4) * 4,
                  &x[(size_t)(tokbase + row) * D_IN + kb + 4 * c4]);
    }
#pragma unroll
    for (int i = 0; i < 3; i++) {                 // w fp16: 96 rows x 8 cp16
        int idx = i * T1 + tid;
        int row = idx >> 3, q = idx & 7;
        const char* src = (const char*)g_whu + (size_t)row * (D_IN * 2)
                        + kb * 2 + q * 16;
        cpasync16(base + 9216u + (uint32_t)(row * 144 + q * 16), src);
    }
}

__global__ __launch_bounds__(T1, 2) void k1_mma(
    const float* __restrict__ x,
    const float* __restrict__ db,
    const float* __restrict__ ntl,
    const float* __restrict__ gb,
    int ntok)
{
    extern __shared__ float sm[];
    const uint32_t sbase = smem_u32(sm);
    float* sInvT = sm + CST_F;
    float* sBias = sInvT + 84;
    float* sGb   = sBias + 84;

    const int tid = threadIdx.x;
    const int lane = tid & 31, wid = tid >> 5;
    const int m0 = (wid & 1) * 16;      // 2 m-warps x 16 rows
    const int n0 = (wid >> 1) * 24;     // 4 n-warps x 24 cols
    const int tokbase = blockIdx.x * 32;

    const int la_row = (lane & 7) + ((lane >> 3) & 1) * 8;
    const int la_col = (lane >> 4) * 8;
    const int lb_row = (lane & 7) + (lane >> 4) * 8;
    const int lb_col = ((lane >> 3) & 1) * 8;

    if (tid < 84) {
        float z = ntl[tid] + 0.5413f;
        float sp = (z > 15.f) ? z : log1pf(__expf(z));
        sInvT[tid] = 1.0f / sp;
        sBias[tid] = db[tid];
    } else if (tid >= 96 && tid < 96 + NTREES) {
        sGb[tid - 96] = gb[tid - 96];
    }

    float acc[3][4];
#pragma unroll
    for (int tn = 0; tn < 3; tn++)
#pragma unroll
        for (int q = 0; q < 4; q++) acc[tn][q] = 0.f;

    k1_stage(sbase, x, tokbase, 0, tid);
    asm volatile("cp.async.commit_group;" ::: "memory");
    k1_stage(sbase + STG1B, x, tokbase, KC1, tid);
    asm volatile("cp.async.commit_group;" ::: "memory");

    const int NCHUNK = D_IN / KC1;   // 16
    for (int ck = 0; ck < NCHUNK; ck++) {
        if (ck + 1 < NCHUNK) {
            asm volatile("cp.async.wait_group 1;" ::: "memory");
        } else {
            asm volatile("cp.async.wait_group 0;" ::: "memory");
        }
        __syncthreads();
        if (ck + 2 < NCHUNK) {
            k1_stage(sbase + (uint32_t)((ck + 2) % 3) * STG1B, x, tokbase,
                     (ck + 2) * KC1, tid);
            asm volatile("cp.async.commit_group;" ::: "memory");
        }

        const float* Xs = sm + (uint32_t)(ck % 3) * (STG1B / 4);
#pragma unroll
        for (int i = 0; i < 2; i++) {
            int idx = i * T1 + tid;
            int row = idx >> 4, c4 = idx & 15;
            float4 v = *(const float4*)&Xs[row * 72 + 4 * c4];
            __half2 h0 = __floats2half2_rn(v.x, v.y);
            __half2 h1 = __floats2half2_rn(v.z, v.w);
            uint32_t off = (uint32_t)(row * 144 + 8 * c4);
            asm volatile("st.shared.v2.b32 [%0], {%1,%2};"
                         :: "r"(sbase + XH_B + off),
                            "r"(*(uint32_t*)&h0), "r"(*(uint32_t*)&h1));
        }
        __syncthreads();

        const uint32_t wb = sbase + (uint32_t)(ck % 3) * STG1B + 9216u;

#pragma unroll
        for (int ks = 0; ks < KC1 / 16; ks++) {
            const int kk = ks * 16;
            uint32_t ah[4], bh[3][2];
            {
                uint32_t ao = (uint32_t)((m0 + la_row) * 144 + (kk + la_col) * 2);
                LDMX4(ah[0], ah[1], ah[2], ah[3], sbase + XH_B + ao);
            }
#pragma unroll
            for (int tn = 0; tn < 3; tn++) {
                uint32_t bo = (uint32_t)((n0 + tn * 8 + lb_row) * 144 + (kk + lb_col) * 2);
                LDMX2(bh[tn][0], bh[tn][1], wb + bo);
            }
#pragma unroll
            for (int tn = 0; tn < 3; tn++)
                MMA_F16(acc[tn], ah, bh[tn]);
        }
    }

    __syncthreads();
    float* Ds = sm;
    {
        const int r = lane >> 2, c = lane & 3;
#pragma unroll
        for (int tn = 0; tn < 3; tn++) {
            float* p = &Ds[(m0 + r) * 100 + n0 + tn * 8 + 2 * c];
            p[0] = acc[tn][0];
            p[1] = acc[tn][1];
            p[8 * 100] = acc[tn][2];
            p[8 * 100 + 1] = acc[tn][3];
        }
    }
    __syncthreads();

    if (tid < 32) {
        const float* d = &Ds[tid * 100];
        float g[NTREES];
        float m = -1e30f;
#pragma unroll
        for (int t = 0; t < NTREES; t++) { g[t] = d[84 + t] + sGb[t]; m = fmaxf(m, g[t]); }
        float s = 0.f;
#pragma unroll
        for (int t = 0; t < NTREES; t++) { g[t] = __expf(g[t] - m); s += g[t]; }
        float inv = 1.0f / s;

        const int tok = tokbase + tid;
        __half2* orow = (__half2*)&g_coefh[(size_t)tok * NCOL];
#pragma unroll
        for (int t = 0; t < NTREES; t++) {
            float w = g[t] * inv;
            float p[NINT];
#pragma unroll
            for (int n = 0; n < NINT; n++) {
                float z = (d[t * 7 + n] + sBias[t * 7 + n]) * sInvT[t * 7 + n];
                p[n] = 1.0f / (1.0f + __expf(-z));
            }
            float a0 = p[0], a1 = 1.f - p[0];
            orow[t * 4 + 0] = __floats2half2_rn(w * a0 * p[1] * p[3],
                                                w * a0 * p[1] * (1.f - p[3]));
            orow[t * 4 + 1] = __floats2half2_rn(w * a0 * (1.f - p[1]) * p[4],
                                                w * a0 * (1.f - p[1]) * (1.f - p[4]));
            orow[t * 4 + 2] = __floats2half2_rn(w * a1 * p[2] * p[5],
                                                w * a1 * p[2] * (1.f - p[5]));
            orow[t * 4 + 3] = __floats2half2_rn(w * a1 * (1.f - p[2]) * p[6],
                                                w * a1 * (1.f - p[2]) * (1.f - p[6]));
        }
    }
}

// ---------------------------------------------------------------------------
// Kernel 2: persistent-B fp16 MMA, 2-stage A pipeline, COALESCED epilogue
//   via fp16 smem stage (64-row double pass -> full-line STG.128).
//   Grid (8 d-tiles, 3 heads, 12 s) = 288 CTAs, 2 CTAs/SM (97.3 KB smem).
// smem (halfs): B @0 (128x104=13312); A0 @13312; A1 @26624;
//   stage @39936 (64 rows x 136 halfs = 8704).  Total 48640 halfs = 97280 B.
// ---------------------------------------------------------------------------
#define T2     256
#define SA2    104
#define BS2H   13312
#define AS2H   13312
#define STGH   39936
#define SGROW  136
#define SMEM2  ((BS2H + 2 * AS2H + 64 * SGROW) * 2)   // 97280 B

__device__ __forceinline__ void k2_stageA(uint32_t base, int tokbase, int tid)
{
#pragma unroll
    for (int i = 0; i < 6; i++) {      // 128 rows x 12 cp16
        int idx = i * T2 + tid;
        int row = idx / 12, q = idx % 12;
        cpasync16(base + (uint32_t)(row * SA2 + q * 8) * 2,
                  &g_coefh[(size_t)(tokbase + row) * NCOL + q * 8]);
    }
}

__global__ __launch_bounds__(T2, 2) void k2_mma(float* __restrict__ out, int ntok)
{
    extern __shared__ __half smh[];
    const uint32_t sbase = smem_u32(smh);
    __half* stage = smh + STGH;

    const int tid = threadIdx.x;
    const int lane = tid & 31, wid = tid >> 5;
    const int mg = wid >> 2;           // 0/1
    const int m0 = mg * 64;
    const int n0 = (wid & 3) * 32;     // 4 n-warps x 32
    const int dbase = blockIdx.x * 128;
    const int h     = blockIdx.y;
    const int s     = blockIdx.z;      // 0..11
    const int niter = (64 - s + 11) / 12;

    const int la_row = (lane & 7) + ((lane >> 3) & 1) * 8;
    const int la_col = (lane >> 4) * 8;
    const int lb_row = (lane & 7) + (lane >> 4) * 8;
    const int lb_col = ((lane >> 3) & 1) * 8;
    const int fr = lane >> 2, fc = lane & 3;

    // prologue: B + A0 in one group
#pragma unroll
    for (int i = 0; i < 6; i++) {
        int idx = i * T2 + tid;
        int row = idx / 12, q = idx % 12;
        cpasync16(sbase + (uint32_t)(row * SA2 + q * 8) * 2,
                  &g_loth[((size_t)h * D_OUTD + dbase + row) * NCOL + q * 8]);
    }
    k2_stageA(sbase + BS2H * 2, s * 128, tid);
    asm volatile("cp.async.commit_group;" ::: "memory");

    for (int it = 0; it < niter; it++) {
        // prefetch next A into opposite buffer (last read iter it-1; all warps
        // past that read thanks to iter it-1's epilogue syncs)
        if (it + 1 < niter) {
            k2_stageA(sbase + (uint32_t)(BS2H + ((it + 1) & 1) * AS2H) * 2,
                      (s + 12 * (it + 1)) * 128, tid);
            asm volatile("cp.async.commit_group;" ::: "memory");
            asm volatile("cp.async.wait_group 1;" ::: "memory");
        } else {
            asm volatile("cp.async.wait_group 0;" ::: "memory");
        }
        __syncthreads();                                    // S1

        const uint32_t Ab = sbase + (uint32_t)(BS2H + (it & 1) * AS2H) * 2;

        float acc[4][4][4];
#pragma unroll
        for (int tm = 0; tm < 4; tm++)
#pragma unroll
            for (int tn = 0; tn < 4; tn++)
#pragma unroll
                for (int q = 0; q < 4; q++) acc[tm][tn][q] = 0.f;

#pragma unroll
        for (int ks = 0; ks < 6; ks++) {
            const int k0h = ks * 16;
            uint32_t a[4][4], b[4][2];
#pragma unroll
            for (int tm = 0; tm < 4; tm++) {
                uint32_t ad = Ab + (uint32_t)((m0 + tm * 16 + la_row) * SA2 + k0h + la_col) * 2;
                LDMX4(a[tm][0], a[tm][1], a[tm][2], a[tm][3], ad);
            }
#pragma unroll
            for (int tp = 0; tp < 2; tp++) {
                uint32_t bd = sbase + (uint32_t)((n0 + tp * 16 + lb_row) * SA2 + k0h + lb_col) * 2;
                LDMX4(b[2 * tp][0], b[2 * tp][1], b[2 * tp + 1][0], b[2 * tp + 1][1], bd);
            }
#pragma unroll
            for (int tm = 0; tm < 4; tm++)
#pragma unroll
                for (int tn = 0; tn < 4; tn++)
                    MMA_F16(acc[tm][tn], a[tm], b[tn]);
        }

        // ---- staged coalesced epilogue: 2 halves of 64 rows ----
        const int tokbase = (s + 12 * it) * 128;
#pragma unroll
        for (int hh = 0; hh < 2; hh++) {
#pragma unroll
            for (int tml = 0; tml < 2; tml++) {
                const int tm = 2 * hh + tml;
                const int sr = mg * 32 + tml * 16 + fr;    // 0..63
#pragma unroll
                for (int tn = 0; tn < 4; tn++) {
                    const int col = n0 + tn * 8 + 2 * fc;
                    __half2 v0 = __floats2half2_rn(acc[tm][tn][0], acc[tm][tn][1]);
                    __half2 v1 = __floats2half2_rn(acc[tm][tn][2], acc[tm][tn][3]);
                    *(__half2*)&stage[sr * SGROW + col] = v0;
                    *(__half2*)&stage[(sr + 8) * SGROW + col] = v1;
                }
            }
            __syncthreads();                                // S2 / S4
#pragma unroll
            for (int j2 = 0; j2 < 8; j2++) {
                int lin = j2 * T2 + tid;                    // 0..2047
                int sr = lin >> 5, q = lin & 31;            // row, 4-float seg
                __half2 w0 = *(const __half2*)&stage[sr * SGROW + 4 * q];
                __half2 w1 = *(const __half2*)&stage[sr * SGROW + 4 * q + 2];
                float2 f0 = __half22float2(w0);
                float2 f1 = __half22float2(w1);
                float4 v; v.x = f0.x; v.y = f0.y; v.z = f1.x; v.w = f1.y;
                int grow = tokbase + (sr >> 5) * 64 + hh * 32 + (sr & 31);
                *(float4*)&out[((size_t)h * ntok + grow) * D_OUTD + dbase + 4 * q] = v;
            }
            if (hh == 0) __syncthreads();                   // S3: reads done before half1 writes
        }
    }
}

// ---------------------------------------------------------------------------
extern "C" void kernel_launch(void* const* d_in, const int* in_sizes, int n_in,
                              void* d_out, int out_size)
{
    const float* x   = (const float*)d_in[0];
    const float* dw  = (const float*)d_in[1];
    const float* db  = (const float*)d_in[2];
    const float* ntl = (const float*)d_in[3];
    const float* lo  = (const float*)d_in[4];
    const float* gw  = (const float*)d_in[5];
    const float* gb  = (const float*)d_in[6];
    float* out = (float*)d_out;

    int ntok = in_sizes[0] / D_IN;   // 8192

    cudaFuncSetAttribute(k1_mma, cudaFuncAttributeMaxDynamicSharedMemorySize, SMEM1);
    cudaFuncSetAttribute(k2_mma, cudaFuncAttributeMaxDynamicSharedMemorySize, SMEM2);

    k_prep<<<NCOL + 288, 256>>>(dw, gw, lo);
    k1_mma<<<ntok / 32, T1, SMEM1>>>(x, db, ntl, gb, ntok);

    dim3 g2(D_OUTD / 128, NHEADS, 12);
    k2_mma<<<g2, T2, SMEM2>>>(out, ntok);
}